// round 7
// baseline (speedup 1.0000x reference)
#include <cuda_runtime.h>
#include <stdint.h>

// Inputs (metadata order):
//  0: vertex_dofs  [V,1]  f32
//  1: edge_dofs    [E,2]  f32
//  2: face_dofs    [C,1]  f32
//  3: y            [C,10,16] f32
//  4: faces        [C,3]  i32
//  5: faces_to_edges [C,3] i32
//  6: edge_orientation [C,3] i32
// Output: [C,16] f32

#define NB 10
#define QPTS 16
#define THREADS 256
#define BLOCKS_PER_SM 4

__global__ __launch_bounds__(THREADS, BLOCKS_PER_SM)
void quadfn_kernel(const float* __restrict__ vertex_dofs,
                   const float* __restrict__ edge_dofs,
                   const float* __restrict__ face_dofs,
                   const float* __restrict__ y,
                   const int*   __restrict__ faces,
                   const int*   __restrict__ f2e,
                   const int*   __restrict__ orient,
                   float*       __restrict__ out,
                   int C, int G)
{
    const int lane = threadIdx.x & 31;
    const int qg   = lane & 3;          // which float4 of Q=16
    const int grp  = lane & ~3;         // group base lane within warp
    const unsigned m = 0xffffffffu;

    const int g0 = (blockIdx.x * THREADS + threadIdx.x) >> 2;  // group id

    // ---- Prologue: gather + shuffle weights for the first cell ----
    float w0, w1, w2, w3, w4, w5, w6, w7, w8, w9;
    {
        float wv = 0.f, wa = 0.f, wb = 0.f, wf = 0.f;
        if (g0 < C) {
            if (qg < 3) {
                int vidx = __ldg(&faces[3 * g0 + qg]);
                int eidx = __ldg(&f2e[3 * g0 + qg]);
                int o    = __ldg(&orient[3 * g0 + qg]);
                wv = __ldg(&vertex_dofs[vidx]);
                float2 ed = __ldg((const float2*)edge_dofs + eidx);
                wa = (o != 0) ? ed.x : ed.y;
                wb = (o != 0) ? ed.y : ed.x;
            } else {
                wf = __ldg(&face_dofs[g0]);
            }
        }
        w0 = __shfl_sync(m, wv, grp + 0);
        w1 = __shfl_sync(m, wv, grp + 1);
        w2 = __shfl_sync(m, wv, grp + 2);
        w3 = __shfl_sync(m, wa, grp + 0);
        w4 = __shfl_sync(m, wb, grp + 0);
        w5 = __shfl_sync(m, wa, grp + 1);
        w6 = __shfl_sync(m, wb, grp + 1);
        w7 = __shfl_sync(m, wa, grp + 2);
        w8 = __shfl_sync(m, wb, grp + 2);
        w9 = __shfl_sync(m, wf, grp + 3);
    }

    // ---- Persistent grid-stride loop, software-pipelined by one cell ----
    // Loop condition is warp-uniform (__any_sync) so the end-of-loop
    // shuffles stay convergent at the tail.
    for (int c = g0; __any_sync(m, c < C); c += G) {
        const int  cn   = c + G;
        const bool act  = (c  < C);
        const bool actn = (cn < C);

        // 1. Independent index loads for the NEXT cell (long-latency,
        //    issue first so the dependent dof loads can go out during
        //    this cell's y latency).
        int   vidx = 0, eidx = 0, o = 1;
        float nwf = 0.f;
        if (actn) {
            if (qg < 3) {
                vidx = __ldg(&faces[3 * cn + qg]);
                eidx = __ldg(&f2e[3 * cn + qg]);
                o    = __ldg(&orient[3 * cn + qg]);
            } else {
                nwf = __ldg(&face_dofs[cn]);
            }
        }

        // 2. Streaming y tile for the CURRENT cell: 10 LDG.128 in flight.
        //    __ldcs = evict-first (zero reuse; keep L2 for dof tables).
        float4 v[NB];
        if (act) {
            const float4* yv = reinterpret_cast<const float4*>(
                                   y + (size_t)c * NB * QPTS) + qg;
            #pragma unroll
            for (int b = 0; b < NB; b++)
                v[b] = __ldcs(yv + b * (QPTS / 4));
        }

        // 3. Dependent dof loads for the NEXT cell (indices are back or
        //    nearly back; these overlap with the FMA phase below).
        float nwv = 0.f, nwa = 0.f, nwb = 0.f;
        if (actn && qg < 3) {
            nwv = __ldg(&vertex_dofs[vidx]);
            float2 ed = __ldg((const float2*)edge_dofs + eidx);
            nwa = (o != 0) ? ed.x : ed.y;
            nwb = (o != 0) ? ed.y : ed.x;
        }

        // 4. Contraction + store for the CURRENT cell.
        if (act) {
            float4 acc;
            acc.x = w0 * v[0].x; acc.y = w0 * v[0].y;
            acc.z = w0 * v[0].z; acc.w = w0 * v[0].w;
            #define ACC(W, B)                       \
                acc.x = fmaf(W, v[B].x, acc.x);     \
                acc.y = fmaf(W, v[B].y, acc.y);     \
                acc.z = fmaf(W, v[B].z, acc.z);     \
                acc.w = fmaf(W, v[B].w, acc.w);
            ACC(w1, 1) ACC(w2, 2) ACC(w3, 3) ACC(w4, 4)
            ACC(w5, 5) ACC(w6, 6) ACC(w7, 7) ACC(w8, 8) ACC(w9, 9)
            #undef ACC
            __stcs(reinterpret_cast<float4*>(out + (size_t)c * QPTS) + qg, acc);
        }

        // 5. Broadcast NEXT cell's weights (gather loads have had the whole
        //    y-latency + FMA phase to complete).
        w0 = __shfl_sync(m, nwv, grp + 0);
        w1 = __shfl_sync(m, nwv, grp + 1);
        w2 = __shfl_sync(m, nwv, grp + 2);
        w3 = __shfl_sync(m, nwa, grp + 0);
        w4 = __shfl_sync(m, nwb, grp + 0);
        w5 = __shfl_sync(m, nwa, grp + 1);
        w6 = __shfl_sync(m, nwb, grp + 1);
        w7 = __shfl_sync(m, nwa, grp + 2);
        w8 = __shfl_sync(m, nwb, grp + 2);
        w9 = __shfl_sync(m, nwf, grp + 3);
    }
}

extern "C" void kernel_launch(void* const* d_in, const int* in_sizes, int n_in,
                              void* d_out, int out_size)
{
    const float* vertex_dofs = (const float*)d_in[0];
    const float* edge_dofs   = (const float*)d_in[1];
    const float* face_dofs   = (const float*)d_in[2];
    const float* y           = (const float*)d_in[3];
    const int*   faces       = (const int*)d_in[4];
    const int*   f2e         = (const int*)d_in[5];
    const int*   orient      = (const int*)d_in[6];
    float*       out         = (float*)d_out;

    // Derive C from y: [C, NB, Q]
    int C = in_sizes[3] / (NB * QPTS);

    int num_sms = 148;
    cudaDeviceGetAttribute(&num_sms, cudaDevAttrMultiProcessorCount, 0);

    int blocks = num_sms * BLOCKS_PER_SM;           // exact residency, persistent
    int G = blocks * (THREADS / 4);                 // total 4-lane groups

    quadfn_kernel<<<blocks, THREADS>>>(vertex_dofs, edge_dofs, face_dofs, y,
                                       faces, f2e, orient, out, C, G);
}